// round 15
// baseline (speedup 1.0000x reference)
#include <cuda_runtime.h>
#include <cuda_bf16.h>
#include <cstdint>

#define BB 256
#define TT 256
#define CP1 129
#define HH 128
#define G1 384
#define PRED_N (BB * (TT - 1) * 128)
#define PAR_N  (BB * TT * 2)

typedef unsigned long long ull;
typedef unsigned int u32;

// ---------------- scratch: __device__ globals -------------------------------
__device__ float g_gi1[(size_t)BB * TT * G1];   // (b,t,384) layer-1 input proj
__device__ float g_out1[(size_t)BB * TT * HH];  // (b,t,128) layer-1 outputs

// ---------------- helpers ----------------------------------------------------
__device__ __forceinline__ ull fma2(ull a, ull b, ull c) {
    ull d; asm("fma.rn.f32x2 %0,%1,%2,%3;" : "=l"(d) : "l"(a), "l"(b), "l"(c));
    return d;
}
__device__ __forceinline__ float2 unpack2(ull v) {
    float lo, hi; asm("mov.b64 {%0,%1},%2;" : "=f"(lo), "=f"(hi) : "l"(v));
    return make_float2(lo, hi);
}
__device__ __forceinline__ float sigf(float v) {
    return __fdividef(1.f, 1.f + __expf(-v));
}
__device__ __forceinline__ float tanh_(float v) {
    return __fdividef(2.f, 1.f + __expf(-2.f * v)) - 1.f;
}
__device__ __forceinline__ u32 f2tf32(float v) {
    u32 r; asm("cvt.rna.tf32.f32 %0, %1;" : "=r"(r) : "f"(v));
    return r;
}

#define MMA_TF32(d, a, b)                                              \
    asm volatile("mma.sync.aligned.m16n8k8.row.col.f32.tf32.tf32.f32 " \
        "{%0,%1,%2,%3}, {%4,%5,%6,%7}, {%8,%9}, {%0,%1,%2,%3};"        \
        : "+f"((d)[0]), "+f"((d)[1]), "+f"((d)[2]), "+f"((d)[3])       \
        : "r"((a)[0]), "r"((a)[1]), "r"((a)[2]), "r"((a)[3]),          \
          "r"((b)[0]), "r"((b)[1]))

__device__ __forceinline__ int a_dest(int r, int c) {
    return (((r >> 4) * 4 + (c >> 3)) << 7) + (((r & 7) * 4 + (c & 3)) << 2)
         + (((r >> 3) & 1) + (((c >> 2) & 1) << 1));
}
__device__ __forceinline__ int b_dest(int r, int c) {
    return (((r >> 3) * 4 + (c >> 3)) << 6) + (((r & 7) * 4 + (c & 3)) << 1)
         + ((c >> 2) & 1);
}

struct GemmSmem {
    __align__(16) float Ah[4096];
    __align__(16) float Al[4096];
    __align__(16) float Bh[2048];
    __align__(16) float Bl[2048];
};

// ---------------- K1: gi1 = x @ Wih1^T + bih1 (R14 best: tf32-3x) -----------
__global__ void __launch_bounds__(256) k_gi1(
        const float* __restrict__ x, const int* __restrict__ lengths,
        const float* __restrict__ Wih1, const float* __restrict__ bih1) {
    int t0 = blockIdx.x * 128, b = blockIdx.y, n0 = blockIdx.z * 64;
    if (t0 >= lengths[b]) return;

    __shared__ GemmSmem sm;
    int tid = threadIdx.x;
    int w = tid >> 5, lane = tid & 31;
    int gid = lane >> 2, tig = lane & 3;
    int mb4 = (w & 3) * 8, nb4 = (w >> 2) * 16;

    float d[2][4][4] = {};
    const float* xb = x + (size_t)(b * TT + t0) * CP1;

    float pa[16], pb[8];
#pragma unroll
    for (int l = 0; l < 16; l++) {
        int idx = tid + l * 256; int r = idx >> 5, c = idx & 31;
        pa[l] = xb[r * CP1 + c];
    }
#pragma unroll
    for (int l = 0; l < 8; l++) {
        int idx = tid + l * 256; int r = idx >> 5, c = idx & 31;
        pb[l] = Wih1[(size_t)(n0 + r) * CP1 + c];
    }

    for (int kc = 0; kc < 128; kc += 32) {
        __syncthreads();
#pragma unroll
        for (int l = 0; l < 16; l++) {
            int idx = tid + l * 256; int r = idx >> 5, c = idx & 31;
            float v = pa[l];
            float hf = __uint_as_float(f2tf32(v));
            int dst = a_dest(r, c);
            sm.Ah[dst] = hf;
            sm.Al[dst] = __uint_as_float(f2tf32(v - hf));
        }
#pragma unroll
        for (int l = 0; l < 8; l++) {
            int idx = tid + l * 256; int r = idx >> 5, c = idx & 31;
            float v = pb[l];
            float hf = __uint_as_float(f2tf32(v));
            int dst = b_dest(r, c);
            sm.Bh[dst] = hf;
            sm.Bl[dst] = __uint_as_float(f2tf32(v - hf));
        }
        __syncthreads();

        if (kc < 96) {
            int kn = kc + 32;
#pragma unroll
            for (int l = 0; l < 16; l++) {
                int idx = tid + l * 256; int r = idx >> 5, c = idx & 31;
                pa[l] = xb[r * CP1 + kn + c];
            }
#pragma unroll
            for (int l = 0; l < 8; l++) {
                int idx = tid + l * 256; int r = idx >> 5, c = idx & 31;
                pb[l] = Wih1[(size_t)(n0 + r) * CP1 + kn + c];
            }
        }

#pragma unroll
        for (int k8 = 0; k8 < 4; k8++) {
            u32 ah[2][4], al[2][4], bh[4][2], bl[4][2];
#pragma unroll
            for (int mt = 0; mt < 2; mt++) {
                int off = ((mb4 + mt * 4 + k8) << 7) + (lane << 2);
                float4 vh = *(const float4*)&sm.Ah[off];
                float4 vl = *(const float4*)&sm.Al[off];
                ah[mt][0] = __float_as_uint(vh.x); ah[mt][1] = __float_as_uint(vh.y);
                ah[mt][2] = __float_as_uint(vh.z); ah[mt][3] = __float_as_uint(vh.w);
                al[mt][0] = __float_as_uint(vl.x); al[mt][1] = __float_as_uint(vl.y);
                al[mt][2] = __float_as_uint(vl.z); al[mt][3] = __float_as_uint(vl.w);
            }
#pragma unroll
            for (int nt = 0; nt < 4; nt++) {
                int off = ((nb4 + nt * 4 + k8) << 6) + (lane << 1);
                float2 vh = *(const float2*)&sm.Bh[off];
                float2 vl = *(const float2*)&sm.Bl[off];
                bh[nt][0] = __float_as_uint(vh.x); bh[nt][1] = __float_as_uint(vh.y);
                bl[nt][0] = __float_as_uint(vl.x); bl[nt][1] = __float_as_uint(vl.y);
            }
#pragma unroll
            for (int mt = 0; mt < 2; mt++)
#pragma unroll
                for (int nt = 0; nt < 4; nt++)
                    MMA_TF32(d[mt][nt], al[mt], bh[nt]);
#pragma unroll
            for (int mt = 0; mt < 2; mt++)
#pragma unroll
                for (int nt = 0; nt < 4; nt++)
                    MMA_TF32(d[mt][nt], ah[mt], bl[nt]);
#pragma unroll
            for (int mt = 0; mt < 2; mt++)
#pragma unroll
                for (int nt = 0; nt < 4; nt++)
                    MMA_TF32(d[mt][nt], ah[mt], bh[nt]);
        }
    }

    int mb = (w & 3) * 32, nb = (w >> 2) * 32;
    float at_[2][2], wt_[4][2], bi_[4][2];
#pragma unroll
    for (int mt = 0; mt < 2; mt++) {
        int r = mb + mt * 16 + gid;
        at_[mt][0] = xb[r * CP1 + 128];
        at_[mt][1] = xb[(r + 8) * CP1 + 128];
    }
#pragma unroll
    for (int nt = 0; nt < 4; nt++) {
        int c0 = n0 + nb + nt * 8 + 2 * tig;
        wt_[nt][0] = Wih1[(size_t)c0 * CP1 + 128];
        wt_[nt][1] = Wih1[(size_t)(c0 + 1) * CP1 + 128];
        bi_[nt][0] = bih1[c0];
        bi_[nt][1] = bih1[c0 + 1];
    }
#pragma unroll
    for (int mt = 0; mt < 2; mt++) {
        int r = mb + mt * 16 + gid;
        float* row0 = g_gi1 + (size_t)(b * TT + t0 + r) * G1 + n0;
        float* row1 = row0 + (size_t)8 * G1;
#pragma unroll
        for (int nt = 0; nt < 4; nt++) {
            int c = nb + nt * 8 + 2 * tig;
            *(float2*)(row0 + c) = make_float2(
                d[mt][nt][0] + at_[mt][0] * wt_[nt][0] + bi_[nt][0],
                d[mt][nt][1] + at_[mt][0] * wt_[nt][1] + bi_[nt][1]);
            *(float2*)(row1 + c) = make_float2(
                d[mt][nt][2] + at_[mt][1] * wt_[nt][0] + bi_[nt][0],
                d[mt][nt][3] + at_[mt][1] * wt_[nt][1] + bi_[nt][1]);
        }
    }
}

// ---------------- K2: fused recurrence, 768 threads, half-rows --------------
// Threads (2g, 2g+1) hold Whh1 row g halves k[0,64)/[64,128) in 32 ull regs.
// shfl_xor(p,1) combines halves in-warp: no extra smem/barriers.
// Gate threads = even tid with row<128 (own reg holds the r-projection).
// gi2 dots on warps 8-13 (Wih2 in smem); layer-2 scalar on thread 767.
__global__ void __launch_bounds__(768, 1)
k_recur1(const int* __restrict__ lengths, const float* __restrict__ h0_1,
         const float* __restrict__ Whh1, const float* __restrict__ bhh1,
         const float* __restrict__ h0_2, const float* __restrict__ Wih2,
         const float* __restrict__ Whh2, const float* __restrict__ bih2,
         const float* __restrict__ bhh2, float* __restrict__ out) {
    int tid = threadIdx.x;               // 0..767
    int row = tid >> 1, half = tid & 1;
    int wid = tid >> 5, lane = tid & 31;
    bool isgate = (half == 0) && (row < HH);

    ull W2h[32];
    const ull* wr = (const ull*)(Whh1 + (size_t)row * HH + half * 64);
#pragma unroll
    for (int i = 0; i < 32; i++) W2h[i] = wr[i];
    float bh = (half == 0) ? bhh1[row] : 0.f;

    __shared__ __align__(16) float s_h[HH];
    __shared__ float s_gh[G1];
    __shared__ float s_gi2[6];
    __shared__ float s_w2[24];            // Whh2(12) + bhh2(6) + bih2(6)
    __shared__ __align__(16) float s_wih2[6 * HH];
    if (tid < 12) s_w2[tid] = Whh2[tid];
    else if (tid < 18) s_w2[tid] = bhh2[tid - 12];
    else if (tid < 24) s_w2[tid] = bih2[tid - 18];
    s_wih2[tid] = Wih2[tid];              // 768 == 6*128 exactly

#pragma unroll 1
    for (int rsel = 0; rsel < 2; rsel++) {
        int b = rsel ? (255 - (int)blockIdx.x) : (int)blockIdx.x;
        int len = lengths[b];
        if (tid < HH) s_h[tid] = h0_1[b * HH + tid];
        float u0 = 0.f, u1 = 0.f;
        if (tid == 767) { u0 = h0_2[b * 2]; u1 = h0_2[b * 2 + 1]; }
        __syncthreads();

        const float* gi = g_gi1 + (size_t)b * TT * G1;
        float* o1 = g_out1 + (size_t)b * TT * HH;
        float* par = out + PRED_N + (size_t)b * TT * 2;
        float pr = 0.f, pz = 0.f, pn = 0.f;
        if (isgate) { pr = gi[row]; pz = gi[HH + row]; pn = gi[2 * HH + row]; }

#pragma unroll 1
        for (int t = 0; t < len; t++) {
            // ---- phase A: gi2 dots (warps 8-13, t>=1), then half-matvec ----
            if (wid >= 8 && wid < 14 && t >= 1) {
                float4 wv = *(const float4*)&s_wih2[(wid - 8) * HH + lane * 4];
                float4 hv = *(const float4*)&s_h[lane * 4];
                float v = hv.x * wv.x + hv.y * wv.y + hv.z * wv.z + hv.w * wv.w;
                v += __shfl_xor_sync(0xFFFFFFFFu, v, 16);
                v += __shfl_xor_sync(0xFFFFFFFFu, v, 8);
                v += __shfl_xor_sync(0xFFFFFFFFu, v, 4);
                v += __shfl_xor_sync(0xFFFFFFFFu, v, 2);
                v += __shfl_xor_sync(0xFFFFFFFFu, v, 1);
                if (lane == 0) s_gi2[wid - 8] = v + s_w2[18 + (wid - 8)];
            }

            ull a0 = 0ull, a1 = 0ull;
            const ull* h2 = (const ull*)s_h + half * 32;
#pragma unroll
            for (int i = 0; i < 32; i += 2) {
                a0 = fma2(W2h[i],     h2[i],     a0);
                a1 = fma2(W2h[i + 1], h2[i + 1], a1);
            }
            float2 f0 = unpack2(a0), f1 = unpack2(a1);
            float p = (f0.x + f0.y) + (f1.x + f1.y);
            p += __shfl_xor_sync(0xFFFFFFFFu, p, 1);   // combine row halves
            float dot = p + bh;                        // full dot + bias (even tid)
            if (half == 0 && row >= HH) s_gh[row] = dot;
            __syncthreads();

            // ---- phase B: gate update | layer-2 scalar GRU -----------------
            if (isgate) {
                float r = sigf(pr + dot);              // r-projection = own row
                float z = sigf(pz + s_gh[HH + row]);
                float n = tanh_(pn + r * s_gh[2 * HH + row]);
                float hn = (1.f - z) * n + z * s_h[row];
                s_h[row] = hn;
                o1[(size_t)t * HH + row] = hn;
                if (t + 1 < len) {
                    const float* gn = gi + (size_t)(t + 1) * G1;
                    pr = gn[row]; pz = gn[HH + row]; pn = gn[2 * HH + row];
                }
            } else if (tid == 767 && t >= 1) {
                float hr0 = s_w2[0]  * u0 + s_w2[1]  * u1 + s_w2[12];
                float hr1 = s_w2[2]  * u0 + s_w2[3]  * u1 + s_w2[13];
                float hz0 = s_w2[4]  * u0 + s_w2[5]  * u1 + s_w2[14];
                float hz1 = s_w2[6]  * u0 + s_w2[7]  * u1 + s_w2[15];
                float hn0 = s_w2[8]  * u0 + s_w2[9]  * u1 + s_w2[16];
                float hn1 = s_w2[10] * u0 + s_w2[11] * u1 + s_w2[17];
                float r0 = sigf(s_gi2[0] + hr0), r1 = sigf(s_gi2[1] + hr1);
                float z0 = sigf(s_gi2[2] + hz0), z1 = sigf(s_gi2[3] + hz1);
                float n0 = tanh_(s_gi2[4] + r0 * hn0), n1 = tanh_(s_gi2[5] + r1 * hn1);
                u0 = (1.f - z0) * n0 + z0 * u0;
                u1 = (1.f - z1) * n1 + z1 * u1;
                par[(t - 1) * 2]     = __expf(-u0);
                par[(t - 1) * 2 + 1] = __expf(-u1);
            }
            __syncthreads();
        }

        // final layer-2 step (uses out1[len-1] == current s_h)
        if (wid >= 8 && wid < 14) {
            float4 wv = *(const float4*)&s_wih2[(wid - 8) * HH + lane * 4];
            float4 hv = *(const float4*)&s_h[lane * 4];
            float v = hv.x * wv.x + hv.y * wv.y + hv.z * wv.z + hv.w * wv.w;
            v += __shfl_xor_sync(0xFFFFFFFFu, v, 16);
            v += __shfl_xor_sync(0xFFFFFFFFu, v, 8);
            v += __shfl_xor_sync(0xFFFFFFFFu, v, 4);
            v += __shfl_xor_sync(0xFFFFFFFFu, v, 2);
            v += __shfl_xor_sync(0xFFFFFFFFu, v, 1);
            if (lane == 0) s_gi2[wid - 8] = v + s_w2[18 + (wid - 8)];
        }
        __syncthreads();
        if (tid == 767) {
            float hr0 = s_w2[0]  * u0 + s_w2[1]  * u1 + s_w2[12];
            float hr1 = s_w2[2]  * u0 + s_w2[3]  * u1 + s_w2[13];
            float hz0 = s_w2[4]  * u0 + s_w2[5]  * u1 + s_w2[14];
            float hz1 = s_w2[6]  * u0 + s_w2[7]  * u1 + s_w2[15];
            float hn0 = s_w2[8]  * u0 + s_w2[9]  * u1 + s_w2[16];
            float hn1 = s_w2[10] * u0 + s_w2[11] * u1 + s_w2[17];
            float r0 = sigf(s_gi2[0] + hr0), r1 = sigf(s_gi2[1] + hr1);
            float z0 = sigf(s_gi2[2] + hz0), z1 = sigf(s_gi2[3] + hz1);
            float n0 = tanh_(s_gi2[4] + r0 * hn0), n1 = tanh_(s_gi2[5] + r1 * hn1);
            u0 = (1.f - z0) * n0 + z0 * u0;
            u1 = (1.f - z1) * n1 + z1 * u1;
            par[(len - 1) * 2]     = __expf(-u0);
            par[(len - 1) * 2 + 1] = __expf(-u1);
        }
        for (int tp = len + tid; tp < TT; tp += 768) {
            par[tp * 2] = 1.f; par[tp * 2 + 1] = 1.f;
        }
        if (tid == 0) out[PRED_N + PAR_N + b] = (float)len;
        __syncthreads();
    }
}

// ---------------- K3: FC head (R14: tf32-3x pipelined, masked) --------------
__global__ void __launch_bounds__(256) k_fc(
        const float* __restrict__ x, const int* __restrict__ lengths,
        const float* __restrict__ Wfc, const float* __restrict__ bfc,
        float* __restrict__ out) {
    int t0 = blockIdx.x * 128, b = blockIdx.y, n0 = blockIdx.z * 64;
    int len = lengths[b];
    float* ob = out + ((size_t)b * (TT - 1)) * 128;
    int rows = min(128, (TT - 1) - t0);

    if (t0 >= len - 1) {
        for (int idx = threadIdx.x; idx < rows * 64; idx += 256) {
            int m = idx >> 6, n = idx & 63;
            ob[(size_t)(t0 + m) * 128 + n0 + n] = 0.f;
        }
        return;
    }

    __shared__ GemmSmem sm;
    int tid = threadIdx.x;
    int w = tid >> 5, lane = tid & 31;
    int gid = lane >> 2, tig = lane & 3;
    int mb4 = (w & 3) * 8, nb4 = (w >> 2) * 16;

    float d[2][4][4] = {};
    const float* ab = g_out1 + (size_t)(b * TT + t0) * HH;

    float pa[16], pb[8];
#pragma unroll
    for (int l = 0; l < 16; l++) {
        int idx = tid + l * 256; int r = idx >> 5, c = idx & 31;
        pa[l] = ab[r * HH + c];
    }
#pragma unroll
    for (int l = 0; l < 8; l++) {
        int idx = tid + l * 256; int r = idx >> 5, c = idx & 31;
        pb[l] = Wfc[(size_t)(n0 + r) * CP1 + c];
    }

    for (int kc = 0; kc < 128; kc += 32) {
        __syncthreads();
#pragma unroll
        for (int l = 0; l < 16; l++) {
            int idx = tid + l * 256; int r = idx >> 5, c = idx & 31;
            float v = pa[l];
            float hf = __uint_as_float(f2tf32(v));
            int dst = a_dest(r, c);
            sm.Ah[dst] = hf;
            sm.Al[dst] = __uint_as_float(f2tf32(v - hf));
        }
#pragma unroll
        for (int l = 0; l < 8; l++) {
            int idx = tid + l * 256; int r = idx >> 5, c = idx & 31;
            float v = pb[l];
            float hf = __uint_as_float(f2tf32(v));
            int dst = b_dest(r, c);
            sm.Bh[dst] = hf;
            sm.Bl[dst] = __uint_as_float(f2tf32(v - hf));
        }
        __syncthreads();

        if (kc < 96) {
            int kn = kc + 32;
#pragma unroll
            for (int l = 0; l < 16; l++) {
                int idx = tid + l * 256; int r = idx >> 5, c = idx & 31;
                pa[l] = ab[r * HH + kn + c];
            }
#pragma unroll
            for (int l = 0; l < 8; l++) {
                int idx = tid + l * 256; int r = idx >> 5, c = idx & 31;
                pb[l] = Wfc[(size_t)(n0 + r) * CP1 + kn + c];
            }
        }

#pragma unroll
        for (int k8 = 0; k8 < 4; k8++) {
            u32 ah[2][4], al[2][4], bh[4][2], bl[4][2];
#pragma unroll
            for (int mt = 0; mt < 2; mt++) {
                int off = ((mb4 + mt * 4 + k8) << 7) + (lane << 2);
                float4 vh = *(const float4*)&sm.Ah[off];
                float4 vl = *(const float4*)&sm.Al[off];
                ah[mt][0] = __float_as_uint(vh.x); ah[mt][1] = __float_as_uint(vh.y);
                ah[mt][2] = __float_as_uint(vh.z); ah[mt][3] = __float_as_uint(vh.w);
                al[mt][0] = __float_as_uint(vl.x); al[mt][1] = __float_as_uint(vl.y);
                al[mt][2] = __float_as_uint(vl.z); al[mt][3] = __float_as_uint(vl.w);
            }
#pragma unroll
            for (int nt = 0; nt < 4; nt++) {
                int off = ((nb4 + nt * 4 + k8) << 6) + (lane << 1);
                float2 vh = *(const float2*)&sm.Bh[off];
                float2 vl = *(const float2*)&sm.Bl[off];
                bh[nt][0] = __float_as_uint(vh.x); bh[nt][1] = __float_as_uint(vh.y);
                bl[nt][0] = __float_as_uint(vl.x); bl[nt][1] = __float_as_uint(vl.y);
            }
#pragma unroll
            for (int mt = 0; mt < 2; mt++)
#pragma unroll
                for (int nt = 0; nt < 4; nt++)
                    MMA_TF32(d[mt][nt], al[mt], bh[nt]);
#pragma unroll
            for (int mt = 0; mt < 2; mt++)
#pragma unroll
                for (int nt = 0; nt < 4; nt++)
                    MMA_TF32(d[mt][nt], ah[mt], bl[nt]);
#pragma unroll
            for (int mt = 0; mt < 2; mt++)
#pragma unroll
                for (int nt = 0; nt < 4; nt++)
                    MMA_TF32(d[mt][nt], ah[mt], bh[nt]);
        }
    }

    int mb = (w & 3) * 32, nb = (w >> 2) * 32;
    float at_[2][2], wt_[4][2], bi_[4][2];
#pragma unroll
    for (int mt = 0; mt < 2; mt++) {
        int r = mb + mt * 16 + gid;
        at_[mt][0] = x[(size_t)(b * TT + t0 + r) * CP1];
        at_[mt][1] = x[(size_t)(b * TT + t0 + r + 8) * CP1];
    }
#pragma unroll
    for (int nt = 0; nt < 4; nt++) {
        int c0 = n0 + nb + nt * 8 + 2 * tig;
        wt_[nt][0] = Wfc[(size_t)c0 * CP1 + 128];
        wt_[nt][1] = Wfc[(size_t)(c0 + 1) * CP1 + 128];
        bi_[nt][0] = bfc[c0];
        bi_[nt][1] = bfc[c0 + 1];
    }
#pragma unroll
    for (int mt = 0; mt < 2; mt++) {
#pragma unroll
        for (int half = 0; half < 2; half++) {
            int r = mb + mt * 16 + gid + half * 8;
            int t = t0 + r;
            if (t >= TT - 1) continue;
            bool valid = (t < len - 1);
            float* row = ob + (size_t)t * 128 + n0;
            float av = at_[mt][half];
#pragma unroll
            for (int nt = 0; nt < 4; nt++) {
                int c = nb + nt * 8 + 2 * tig;
                float v0 = d[mt][nt][half * 2]     + av * wt_[nt][0] + bi_[nt][0];
                float v1 = d[mt][nt][half * 2 + 1] + av * wt_[nt][1] + bi_[nt][1];
                *(float2*)(row + c) = valid ? make_float2(v0, v1)
                                            : make_float2(0.f, 0.f);
            }
        }
    }
}

// ---------------- launch -----------------------------------------------------
extern "C" void kernel_launch(void* const* d_in, const int* in_sizes, int n_in,
                              void* d_out, int out_size) {
    const float* x      = (const float*)d_in[0];
    const int*   lens   = (const int*)  d_in[1];
    const float* h0_1   = (const float*)d_in[2];
    const float* h0_2   = (const float*)d_in[3];
    const float* Wih1   = (const float*)d_in[4];
    const float* Whh1   = (const float*)d_in[5];
    const float* bih1   = (const float*)d_in[6];
    const float* bhh1   = (const float*)d_in[7];
    const float* Wih2   = (const float*)d_in[8];
    const float* Whh2   = (const float*)d_in[9];
    const float* bih2   = (const float*)d_in[10];
    const float* bhh2   = (const float*)d_in[11];
    const float* Wfc    = (const float*)d_in[12];
    const float* bfc    = (const float*)d_in[13];
    float* out = (float*)d_out;

    k_gi1  <<<dim3(2, BB, 6), 256>>>(x, lens, Wih1, bih1);
    k_recur1<<<128, 768>>>(lens, h0_1, Whh1, bhh1, h0_2, Wih2, Whh2, bih2, bhh2, out);
    k_fc   <<<dim3(2, BB, 2), 256>>>(x, lens, Wfc, bfc, out);
}

// round 16
// speedup vs baseline: 2.2432x; 2.2432x over previous
#include <cuda_runtime.h>
#include <cuda_bf16.h>
#include <cstdint>

#define BB 256
#define TT 256
#define CP1 129
#define HH 128
#define G1 384
#define PRED_N (BB * (TT - 1) * 128)
#define PAR_N  (BB * TT * 2)

typedef unsigned long long ull;
typedef unsigned int u32;

// ---------------- scratch: __device__ globals -------------------------------
__device__ float g_gi1[(size_t)BB * TT * G1];   // (b,t,384) layer-1 input proj
__device__ float g_out1[(size_t)BB * TT * HH];  // (b,t,128) layer-1 outputs

// ---------------- helpers ----------------------------------------------------
__device__ __forceinline__ ull fma2(ull a, ull b, ull c) {
    ull d; asm("fma.rn.f32x2 %0,%1,%2,%3;" : "=l"(d) : "l"(a), "l"(b), "l"(c));
    return d;
}
__device__ __forceinline__ float2 unpack2(ull v) {
    float lo, hi; asm("mov.b64 {%0,%1},%2;" : "=f"(lo), "=f"(hi) : "l"(v));
    return make_float2(lo, hi);
}
__device__ __forceinline__ float sigf(float v) {
    return __fdividef(1.f, 1.f + __expf(-v));
}
__device__ __forceinline__ float tanh_(float v) {
    return __fdividef(2.f, 1.f + __expf(-2.f * v)) - 1.f;
}
__device__ __forceinline__ u32 f2tf32(float v) {
    u32 r; asm("cvt.rna.tf32.f32 %0, %1;" : "=r"(r) : "f"(v));
    return r;
}
// split (v0,v1) into packed bf16x2 hi + residual bf16x2 lo (k-even=low half)
__device__ __forceinline__ void bf16split(float v0, float v1, u32& hi, u32& lo) {
    __nv_bfloat16 h0 = __float2bfloat16(v0), h1 = __float2bfloat16(v1);
    float r0 = v0 - __bfloat162float(h0);
    float r1 = v1 - __bfloat162float(h1);
    __nv_bfloat162 hp = __halves2bfloat162(h0, h1);
    __nv_bfloat162 lp = __halves2bfloat162(__float2bfloat16(r0), __float2bfloat16(r1));
    hi = *(u32*)&hp; lo = *(u32*)&lp;
}

#define MMA_TF32(d, a, b)                                              \
    asm volatile("mma.sync.aligned.m16n8k8.row.col.f32.tf32.tf32.f32 " \
        "{%0,%1,%2,%3}, {%4,%5,%6,%7}, {%8,%9}, {%0,%1,%2,%3};"        \
        : "+f"((d)[0]), "+f"((d)[1]), "+f"((d)[2]), "+f"((d)[3])       \
        : "r"((a)[0]), "r"((a)[1]), "r"((a)[2]), "r"((a)[3]),          \
          "r"((b)[0]), "r"((b)[1]))

#define MMA_BF16(d, a, b)                                                  \
    asm volatile("mma.sync.aligned.m16n8k16.row.col.f32.bf16.bf16.f32 "    \
        "{%0,%1,%2,%3}, {%4,%5,%6,%7}, {%8,%9}, {%0,%1,%2,%3};"            \
        : "+f"((d)[0]), "+f"((d)[1]), "+f"((d)[2]), "+f"((d)[3])           \
        : "r"((a)[0]), "r"((a)[1]), "r"((a)[2]), "r"((a)[3]),              \
          "r"((b)[0]), "r"((b)[1]))

// tf32 packed maps (K-chunk 32) — used by k_fc (unchanged R13 path)
__device__ __forceinline__ int a_dest(int r, int c) {
    return (((r >> 4) * 4 + (c >> 3)) << 7) + (((r & 7) * 4 + (c & 3)) << 2)
         + (((r >> 3) & 1) + (((c >> 2) & 1) << 1));
}
__device__ __forceinline__ int b_dest(int r, int c) {
    return (((r >> 3) * 4 + (c >> 3)) << 6) + (((r & 7) * 4 + (c & 3)) << 1)
         + ((c >> 2) & 1);
}

struct GemmSmem {           // tf32 (k_fc)
    __align__(16) float Ah[4096];
    __align__(16) float Al[4096];
    __align__(16) float Bh[2048];
    __align__(16) float Bl[2048];
};
struct GemmSmemBf {         // bf16 packed u32 (k_gi1)
    __align__(16) u32 Ah[2048];
    __align__(16) u32 Al[2048];
    __align__(16) u32 Bh[1024];
    __align__(16) u32 Bl[1024];
};

// ---------------- K1: gi1 = x @ Wih1^T + bih1  (bf16-3x, m16n8k16) ----------
// Tile 128m x 64n, K-chunk 32 (= 2 k16 groups). Fragment-packed u32 layout:
//  A pair (r,c2): dst = ((r>>4)*2+(c2>>3))*128 + ((r&7)*4+(c2&3))*4
//                       + ((r>>3)&1) + 2*((c2>>2)&1)          -> LDS.128 frag
//  B pair (n,c2): dst = ((n>>3)*2+(c2>>3))*64 + ((n&7)*4+(c2&3))*2
//                       + ((c2>>2)&1)                          -> LDS.64 frag
__global__ void __launch_bounds__(256) k_gi1(
        const float* __restrict__ x, const int* __restrict__ lengths,
        const float* __restrict__ Wih1, const float* __restrict__ bih1) {
    int t0 = blockIdx.x * 128, b = blockIdx.y, n0 = blockIdx.z * 64;
    if (t0 >= lengths[b]) return;

    __shared__ GemmSmemBf sm;
    int tid = threadIdx.x;
    int w = tid >> 5, lane = tid & 31;
    int gid = lane >> 2, tig = lane & 3;

    float d[2][4][4] = {};
    const float* xb = x + (size_t)(b * TT + t0) * CP1;

    // prefetch chunk 0 raw floats
    float pa[16], pb[8];
#pragma unroll
    for (int l = 0; l < 8; l++) {
        int idx = tid + l * 256; int r = idx >> 4, c2 = idx & 15;
        int base = r * CP1 + 2 * c2;
        pa[2 * l] = xb[base]; pa[2 * l + 1] = xb[base + 1];
    }
#pragma unroll
    for (int l = 0; l < 4; l++) {
        int idx = tid + l * 256; int n = idx >> 4, c2 = idx & 15;
        int base = (n0 + n) * CP1 + 2 * c2;
        pb[2 * l] = Wih1[(size_t)base]; pb[2 * l + 1] = Wih1[(size_t)base + 1];
    }

    for (int kc = 0; kc < 128; kc += 32) {
        __syncthreads();
#pragma unroll
        for (int l = 0; l < 8; l++) {            // A: 2048 u32
            int idx = tid + l * 256; int r = idx >> 4, c2 = idx & 15;
            u32 hi, lo; bf16split(pa[2 * l], pa[2 * l + 1], hi, lo);
            int dst = (((r >> 4) * 2 + (c2 >> 3)) << 7)
                    + (((r & 7) * 4 + (c2 & 3)) << 2)
                    + ((r >> 3) & 1) + (((c2 >> 2) & 1) << 1);
            sm.Ah[dst] = hi; sm.Al[dst] = lo;
        }
#pragma unroll
        for (int l = 0; l < 4; l++) {            // B: 1024 u32
            int idx = tid + l * 256; int n = idx >> 4, c2 = idx & 15;
            u32 hi, lo; bf16split(pb[2 * l], pb[2 * l + 1], hi, lo);
            int dst = (((n >> 3) * 2 + (c2 >> 3)) << 6)
                    + (((n & 7) * 4 + (c2 & 3)) << 1)
                    + ((c2 >> 2) & 1);
            sm.Bh[dst] = hi; sm.Bl[dst] = lo;
        }
        __syncthreads();

        if (kc < 96) {   // prefetch next chunk while MMAs run
            int kn = kc + 32;
#pragma unroll
            for (int l = 0; l < 8; l++) {
                int idx = tid + l * 256; int r = idx >> 4, c2 = idx & 15;
                int base = r * CP1 + kn + 2 * c2;
                pa[2 * l] = xb[base]; pa[2 * l + 1] = xb[base + 1];
            }
#pragma unroll
            for (int l = 0; l < 4; l++) {
                int idx = tid + l * 256; int n = idx >> 4, c2 = idx & 15;
                int base = (n0 + n) * CP1 + kn + 2 * c2;
                pb[2 * l] = Wih1[(size_t)base]; pb[2 * l + 1] = Wih1[(size_t)base + 1];
            }
        }

#pragma unroll
        for (int kh = 0; kh < 2; kh++) {
            u32 ah[2][4], al[2][4], bh_[4][2], bl_[4][2];
#pragma unroll
            for (int mt = 0; mt < 2; mt++) {
                int off = ((((w & 3) * 2 + mt) * 2 + kh) << 7) + (lane << 2);
                uint4 vh = *(const uint4*)&sm.Ah[off];
                uint4 vl = *(const uint4*)&sm.Al[off];
                ah[mt][0] = vh.x; ah[mt][1] = vh.y; ah[mt][2] = vh.z; ah[mt][3] = vh.w;
                al[mt][0] = vl.x; al[mt][1] = vl.y; al[mt][2] = vl.z; al[mt][3] = vl.w;
            }
#pragma unroll
            for (int nt = 0; nt < 4; nt++) {
                int off = ((((w >> 2) * 4 + nt) * 2 + kh) << 6) + (lane << 1);
                uint2 vh = *(const uint2*)&sm.Bh[off];
                uint2 vl = *(const uint2*)&sm.Bl[off];
                bh_[nt][0] = vh.x; bh_[nt][1] = vh.y;
                bl_[nt][0] = vl.x; bl_[nt][1] = vl.y;
            }
#pragma unroll
            for (int mt = 0; mt < 2; mt++)
#pragma unroll
                for (int nt = 0; nt < 4; nt++)
                    MMA_BF16(d[mt][nt], al[mt], bh_[nt]);
#pragma unroll
            for (int mt = 0; mt < 2; mt++)
#pragma unroll
                for (int nt = 0; nt < 4; nt++)
                    MMA_BF16(d[mt][nt], ah[mt], bl_[nt]);
#pragma unroll
            for (int mt = 0; mt < 2; mt++)
#pragma unroll
                for (int nt = 0; nt < 4; nt++)
                    MMA_BF16(d[mt][nt], ah[mt], bh_[nt]);
        }
    }

    // epilogue: k=128 tail + bias + store (fp32) — D layout same as k8
    int mb = (w & 3) * 32, nb = (w >> 2) * 32;
    float at_[2][2], wt_[4][2], bi_[4][2];
#pragma unroll
    for (int mt = 0; mt < 2; mt++) {
        int r = mb + mt * 16 + gid;
        at_[mt][0] = xb[r * CP1 + 128];
        at_[mt][1] = xb[(r + 8) * CP1 + 128];
    }
#pragma unroll
    for (int nt = 0; nt < 4; nt++) {
        int c0 = n0 + nb + nt * 8 + 2 * tig;
        wt_[nt][0] = Wih1[(size_t)c0 * CP1 + 128];
        wt_[nt][1] = Wih1[(size_t)(c0 + 1) * CP1 + 128];
        bi_[nt][0] = bih1[c0];
        bi_[nt][1] = bih1[c0 + 1];
    }
#pragma unroll
    for (int mt = 0; mt < 2; mt++) {
        int r = mb + mt * 16 + gid;
        float* row0 = g_gi1 + (size_t)(b * TT + t0 + r) * G1 + n0;
        float* row1 = row0 + (size_t)8 * G1;
#pragma unroll
        for (int nt = 0; nt < 4; nt++) {
            int c = nb + nt * 8 + 2 * tig;
            *(float2*)(row0 + c) = make_float2(
                d[mt][nt][0] + at_[mt][0] * wt_[nt][0] + bi_[nt][0],
                d[mt][nt][1] + at_[mt][0] * wt_[nt][1] + bi_[nt][1]);
            *(float2*)(row1 + c) = make_float2(
                d[mt][nt][2] + at_[mt][1] * wt_[nt][0] + bi_[nt][0],
                d[mt][nt][3] + at_[mt][1] * wt_[nt][1] + bi_[nt][1]);
        }
    }
}

// ---------------- K2: fused recurrence (EXACT R13 — frozen) -----------------
__global__ void __launch_bounds__(384, 1)
k_recur1(const int* __restrict__ lengths, const float* __restrict__ h0_1,
         const float* __restrict__ Whh1, const float* __restrict__ bhh1,
         const float* __restrict__ h0_2, const float* __restrict__ Wih2,
         const float* __restrict__ Whh2, const float* __restrict__ bih2,
         const float* __restrict__ bhh2, float* __restrict__ out) {
    int g = threadIdx.x;
    int wid = g >> 5, lane = g & 31;
    ull W2[64];
    const ull* wr = (const ull*)(Whh1 + (size_t)g * HH);
#pragma unroll
    for (int i = 0; i < 64; i++) W2[i] = wr[i];
    float bh = bhh1[g];

    float4 wv2 = make_float4(0.f, 0.f, 0.f, 0.f);
    float bi2 = 0.f;
    if (wid < 6) { wv2 = ((const float4*)Wih2)[wid * 32 + lane]; bi2 = bih2[wid]; }

    __shared__ __align__(16) float s_h[HH];
    __shared__ float s_gh[G1];
    __shared__ float s_gi2[6];
    __shared__ float s_w2[18];
    if (g < 12) s_w2[g] = Whh2[g];
    else if (g < 18) s_w2[g] = bhh2[g - 12];

#pragma unroll 1
    for (int rsel = 0; rsel < 2; rsel++) {
        int b = rsel ? (255 - (int)blockIdx.x) : (int)blockIdx.x;
        int len = lengths[b];
        if (g < HH) s_h[g] = h0_1[b * HH + g];
        float u0 = 0.f, u1 = 0.f;
        if (g == 383) { u0 = h0_2[b * 2]; u1 = h0_2[b * 2 + 1]; }
        __syncthreads();

        const float* gi = g_gi1 + (size_t)b * TT * G1;
        float* o1 = g_out1 + (size_t)b * TT * HH;
        float* par = out + PRED_N + (size_t)b * TT * 2;
        float pr = 0.f, pz = 0.f, pn = 0.f;
        if (g < HH) { pr = gi[g]; pz = gi[HH + g]; pn = gi[2 * HH + g]; }

#pragma unroll 1
        for (int t = 0; t < len; t++) {
            if (wid < 6 && t >= 1) {
                float4 hv = *(const float4*)&s_h[lane * 4];
                float v = hv.x * wv2.x + hv.y * wv2.y + hv.z * wv2.z + hv.w * wv2.w;
                v += __shfl_xor_sync(0xFFFFFFFFu, v, 16);
                v += __shfl_xor_sync(0xFFFFFFFFu, v, 8);
                v += __shfl_xor_sync(0xFFFFFFFFu, v, 4);
                v += __shfl_xor_sync(0xFFFFFFFFu, v, 2);
                v += __shfl_xor_sync(0xFFFFFFFFu, v, 1);
                if (lane == 0) s_gi2[wid] = v + bi2;
            }

            ull a0 = 0ull, a1 = 0ull, a2 = 0ull, a3 = 0ull;
            const ull* h2 = (const ull*)s_h;
#pragma unroll
            for (int i = 0; i < 64; i += 4) {
                a0 = fma2(W2[i],     h2[i],     a0);
                a1 = fma2(W2[i + 1], h2[i + 1], a1);
                a2 = fma2(W2[i + 2], h2[i + 2], a2);
                a3 = fma2(W2[i + 3], h2[i + 3], a3);
            }
            float2 f0 = unpack2(a0), f1 = unpack2(a1);
            float2 f2 = unpack2(a2), f3 = unpack2(a3);
            s_gh[g] = ((f0.x + f0.y) + (f1.x + f1.y)) +
                      ((f2.x + f2.y) + (f3.x + f3.y)) + bh;
            __syncthreads();

            if (g < HH) {
                float r = sigf(pr + s_gh[g]);
                float z = sigf(pz + s_gh[HH + g]);
                float n = tanh_(pn + r * s_gh[2 * HH + g]);
                float hn = (1.f - z) * n + z * s_h[g];
                o1[(size_t)t * HH + g] = hn;
                if (t + 1 < len) {
                    const float* gn = gi + (size_t)(t + 1) * G1;
                    pr = gn[g]; pz = gn[HH + g]; pn = gn[2 * HH + g];
                }
                s_h[g] = hn;
            } else if (g == 383 && t >= 1) {
                float hr0 = s_w2[0]  * u0 + s_w2[1]  * u1 + s_w2[12];
                float hr1 = s_w2[2]  * u0 + s_w2[3]  * u1 + s_w2[13];
                float hz0 = s_w2[4]  * u0 + s_w2[5]  * u1 + s_w2[14];
                float hz1 = s_w2[6]  * u0 + s_w2[7]  * u1 + s_w2[15];
                float hn0 = s_w2[8]  * u0 + s_w2[9]  * u1 + s_w2[16];
                float hn1 = s_w2[10] * u0 + s_w2[11] * u1 + s_w2[17];
                float r0 = sigf(s_gi2[0] + hr0), r1 = sigf(s_gi2[1] + hr1);
                float z0 = sigf(s_gi2[2] + hz0), z1 = sigf(s_gi2[3] + hz1);
                float n0 = tanh_(s_gi2[4] + r0 * hn0), n1 = tanh_(s_gi2[5] + r1 * hn1);
                u0 = (1.f - z0) * n0 + z0 * u0;
                u1 = (1.f - z1) * n1 + z1 * u1;
                par[(t - 1) * 2]     = __expf(-u0);
                par[(t - 1) * 2 + 1] = __expf(-u1);
            }
            __syncthreads();
        }

        if (wid < 6) {
            float4 hv = *(const float4*)&s_h[lane * 4];
            float v = hv.x * wv2.x + hv.y * wv2.y + hv.z * wv2.z + hv.w * wv2.w;
            v += __shfl_xor_sync(0xFFFFFFFFu, v, 16);
            v += __shfl_xor_sync(0xFFFFFFFFu, v, 8);
            v += __shfl_xor_sync(0xFFFFFFFFu, v, 4);
            v += __shfl_xor_sync(0xFFFFFFFFu, v, 2);
            v += __shfl_xor_sync(0xFFFFFFFFu, v, 1);
            if (lane == 0) s_gi2[wid] = v + bi2;
        }
        __syncthreads();
        if (g == 383) {
            float hr0 = s_w2[0]  * u0 + s_w2[1]  * u1 + s_w2[12];
            float hr1 = s_w2[2]  * u0 + s_w2[3]  * u1 + s_w2[13];
            float hz0 = s_w2[4]  * u0 + s_w2[5]  * u1 + s_w2[14];
            float hz1 = s_w2[6]  * u0 + s_w2[7]  * u1 + s_w2[15];
            float hn0 = s_w2[8]  * u0 + s_w2[9]  * u1 + s_w2[16];
            float hn1 = s_w2[10] * u0 + s_w2[11] * u1 + s_w2[17];
            float r0 = sigf(s_gi2[0] + hr0), r1 = sigf(s_gi2[1] + hr1);
            float z0 = sigf(s_gi2[2] + hz0), z1 = sigf(s_gi2[3] + hz1);
            float n0 = tanh_(s_gi2[4] + r0 * hn0), n1 = tanh_(s_gi2[5] + r1 * hn1);
            u0 = (1.f - z0) * n0 + z0 * u0;
            u1 = (1.f - z1) * n1 + z1 * u1;
            par[(len - 1) * 2]     = __expf(-u0);
            par[(len - 1) * 2 + 1] = __expf(-u1);
        }
        for (int tp = len + g; tp < TT; tp += 384) {
            par[tp * 2] = 1.f; par[tp * 2 + 1] = 1.f;
        }
        if (g == 0) out[PRED_N + PAR_N + b] = (float)len;
        __syncthreads();
    }
}

// ---------------- K3: FC head (EXACT R13 tf32-3x, known good) ---------------
__global__ void __launch_bounds__(256) k_fc(
        const float* __restrict__ x, const int* __restrict__ lengths,
        const float* __restrict__ Wfc, const float* __restrict__ bfc,
        float* __restrict__ out) {
    int t0 = blockIdx.x * 128, b = blockIdx.y, n0 = blockIdx.z * 64;
    int len = lengths[b];
    float* ob = out + ((size_t)b * (TT - 1)) * 128;
    int rows = min(128, (TT - 1) - t0);

    if (t0 >= len - 1) {
        for (int idx = threadIdx.x; idx < rows * 64; idx += 256) {
            int m = idx >> 6, n = idx & 63;
            ob[(size_t)(t0 + m) * 128 + n0 + n] = 0.f;
        }
        return;
    }

    __shared__ GemmSmem sm;
    int tid = threadIdx.x;
    int w = tid >> 5, lane = tid & 31;
    int gid = lane >> 2, tig = lane & 3;
    int mb4 = (w & 3) * 8, nb4 = (w >> 2) * 16;

    float d[2][4][4] = {};
    const float* ab = g_out1 + (size_t)(b * TT + t0) * HH;

    for (int kc = 0; kc < 128; kc += 32) {
        __syncthreads();
#pragma unroll
        for (int l = 0; l < 16; l++) {
            int idx = tid + l * 256; int r = idx >> 5, c = idx & 31;
            float v = ab[r * HH + kc + c];
            float hf = __uint_as_float(f2tf32(v));
            int dst = a_dest(r, c);
            sm.Ah[dst] = hf;
            sm.Al[dst] = __uint_as_float(f2tf32(v - hf));
        }
#pragma unroll
        for (int l = 0; l < 8; l++) {
            int idx = tid + l * 256; int r = idx >> 5, c = idx & 31;
            float v = Wfc[(size_t)(n0 + r) * CP1 + kc + c];
            float hf = __uint_as_float(f2tf32(v));
            int dst = b_dest(r, c);
            sm.Bh[dst] = hf;
            sm.Bl[dst] = __uint_as_float(f2tf32(v - hf));
        }
        __syncthreads();
#pragma unroll
        for (int k8 = 0; k8 < 4; k8++) {
            u32 ah[2][4], al[2][4], bh[4][2], bl[4][2];
#pragma unroll
            for (int mt = 0; mt < 2; mt++) {
                int off = ((mb4 + mt * 4 + k8) << 7) + (lane << 2);
                float4 vh = *(const float4*)&sm.Ah[off];
                float4 vl = *(const float4*)&sm.Al[off];
                ah[mt][0] = __float_as_uint(vh.x); ah[mt][1] = __float_as_uint(vh.y);
                ah[mt][2] = __float_as_uint(vh.z); ah[mt][3] = __float_as_uint(vh.w);
                al[mt][0] = __float_as_uint(vl.x); al[mt][1] = __float_as_uint(vl.y);
                al[mt][2] = __float_as_uint(vl.z); al[mt][3] = __float_as_uint(vl.w);
            }
#pragma unroll
            for (int nt = 0; nt < 4; nt++) {
                int off = ((nb4 + nt * 4 + k8) << 6) + (lane << 1);
                float2 vh = *(const float2*)&sm.Bh[off];
                float2 vl = *(const float2*)&sm.Bl[off];
                bh[nt][0] = __float_as_uint(vh.x); bh[nt][1] = __float_as_uint(vh.y);
                bl[nt][0] = __float_as_uint(vl.x); bl[nt][1] = __float_as_uint(vl.y);
            }
#pragma unroll
            for (int mt = 0; mt < 2; mt++)
#pragma unroll
                for (int nt = 0; nt < 4; nt++) {
                    MMA_TF32(d[mt][nt], al[mt], bh[nt]);
                    MMA_TF32(d[mt][nt], ah[mt], bl[nt]);
                    MMA_TF32(d[mt][nt], ah[mt], bh[nt]);
                }
        }
    }

    int mb = (w & 3) * 32, nb = (w >> 2) * 32;
    float at_[2][2], wt_[4][2], bi_[4][2];
#pragma unroll
    for (int mt = 0; mt < 2; mt++) {
        int r = mb + mt * 16 + gid;
        at_[mt][0] = x[(size_t)(b * TT + t0 + r) * CP1];
        at_[mt][1] = x[(size_t)(b * TT + t0 + r + 8) * CP1];
    }
#pragma unroll
    for (int nt = 0; nt < 4; nt++) {
        int c0 = n0 + nb + nt * 8 + 2 * tig;
        wt_[nt][0] = Wfc[(size_t)c0 * CP1 + 128];
        wt_[nt][1] = Wfc[(size_t)(c0 + 1) * CP1 + 128];
        bi_[nt][0] = bfc[c0];
        bi_[nt][1] = bfc[c0 + 1];
    }
#pragma unroll
    for (int mt = 0; mt < 2; mt++) {
#pragma unroll
        for (int half = 0; half < 2; half++) {
            int r = mb + mt * 16 + gid + half * 8;
            int t = t0 + r;
            if (t >= TT - 1) continue;
            bool valid = (t < len - 1);
            float* row = ob + (size_t)t * 128 + n0;
            float av = at_[mt][half];
#pragma unroll
            for (int nt = 0; nt < 4; nt++) {
                int c = nb + nt * 8 + 2 * tig;
                float v0 = d[mt][nt][half * 2]     + av * wt_[nt][0] + bi_[nt][0];
                float v1 = d[mt][nt][half * 2 + 1] + av * wt_[nt][1] + bi_[nt][1];
                *(float2*)(row + c) = valid ? make_float2(v0, v1)
                                            : make_float2(0.f, 0.f);
            }
        }
    }
}

// ---------------- launch -----------------------------------------------------
extern "C" void kernel_launch(void* const* d_in, const int* in_sizes, int n_in,
                              void* d_out, int out_size) {
    const float* x      = (const float*)d_in[0];
    const int*   lens   = (const int*)  d_in[1];
    const float* h0_1   = (const float*)d_in[2];
    const float* h0_2   = (const float*)d_in[3];
    const float* Wih1   = (const float*)d_in[4];
    const float* Whh1   = (const float*)d_in[5];
    const float* bih1   = (const float*)d_in[6];
    const float* bhh1   = (const float*)d_in[7];
    const float* Wih2   = (const float*)d_in[8];
    const float* Whh2   = (const float*)d_in[9];
    const float* bih2   = (const float*)d_in[10];
    const float* bhh2   = (const float*)d_in[11];
    const float* Wfc    = (const float*)d_in[12];
    const float* bfc    = (const float*)d_in[13];
    float* out = (float*)d_out;

    k_gi1  <<<dim3(2, BB, 6), 256>>>(x, lens, Wih1, bih1);
    k_recur1<<<128, 384>>>(lens, h0_1, Whh1, bhh1, h0_2, Wih2, Whh2, bih2, bhh2, out);
    k_fc   <<<dim3(2, BB, 2), 256>>>(x, lens, Wfc, bfc, out);
}